// round 6
// baseline (speedup 1.0000x reference)
#include <cuda_runtime.h>
#include <cuda_bf16.h>

typedef unsigned long long u64;

#define B_SZ   2
#define T_SZ   2048
#define DIM_   2048
#define NHEAD  16
#define KVHEAD 4
#define HDIM   128
#define MROWS  (B_SZ * T_SZ)        // 4096
#define KVDIM  (KVHEAD * HDIM)      // 512

// -------- scratch (device globals; no allocations allowed) --------
__device__ float g_q[(size_t)MROWS * DIM_];    // 32 MB
__device__ float g_k[(size_t)MROWS * KVDIM];   // 8 MB
__device__ float g_v[(size_t)MROWS * KVDIM];   // 8 MB
__device__ float g_att[(size_t)MROWS * DIM_];  // 32 MB

// -------- packed f32x2 helpers (Blackwell FFMA2 pipe) --------
__device__ __forceinline__ u64 pk2(float lo, float hi) {
    u64 r; asm("mov.b64 %0, {%1,%2};" : "=l"(r) : "f"(lo), "f"(hi)); return r;
}
__device__ __forceinline__ void upk2(u64 v, float& lo, float& hi) {
    asm("mov.b64 {%0,%1}, %2;" : "=f"(lo), "=f"(hi) : "l"(v));
}
__device__ __forceinline__ u64 fma2(u64 a, u64 b, u64 c) {
    u64 d; asm("fma.rn.f32x2 %0, %1, %2, %3;" : "=l"(d) : "l"(a), "l"(b), "l"(c)); return d;
}
__device__ __forceinline__ u64 mul2(u64 a, u64 b) {
    u64 d; asm("mul.rn.f32x2 %0, %1, %2;" : "=l"(d) : "l"(a), "l"(b)); return d;
}

// =====================================================================
// SGEMM: C[M,N] = A[M,K] @ W[K,N], row-major. BM=BN=128, BK=16,
// 256 threads, 8x8 per thread, f32x2 packed accumulators (pairs along N).
// Optional fused RoPE epilogue (pairs (2p, 2p+1) inside a head of 128).
// =====================================================================
template<bool ROPE>
__global__ __launch_bounds__(256, 2)
void sgemm_kernel(const float* __restrict__ A, const float* __restrict__ W,
                  float* __restrict__ C, int N, int K,
                  const float* __restrict__ fc, const float* __restrict__ fs)
{
    __shared__ float As[16][132];   // A tile stored transposed: As[k][m]
    __shared__ float Bs[16][132];   // B tile row-major: Bs[k][n]

    const int tid  = threadIdx.x;
    const int tx   = tid & 15;
    const int ty   = tid >> 4;
    const int row0 = blockIdx.y << 7;
    const int col0 = blockIdx.x << 7;

    // load indices: A tile 128x16 = 512 float4 (2/thread), B tile 16x128 = 512 float4
    const int ar = tid >> 2;
    const int ac = (tid & 3) << 2;
    const int bk = tid >> 5;
    const int bc = (tid & 31) << 2;

    u64 acc[8][4];
    #pragma unroll
    for (int i = 0; i < 8; i++)
        #pragma unroll
        for (int j = 0; j < 4; j++) acc[i][j] = 0ull;

    const float* Ab = A + (size_t)row0 * K;
    const float* Wb = W + col0;

    // preload tile 0
    float4 va0 = *(const float4*)(Ab + (size_t)ar * K + ac);
    float4 va1 = *(const float4*)(Ab + (size_t)(ar + 64) * K + ac);
    float4 vb0 = *(const float4*)(Wb + (size_t)bk * N + bc);
    float4 vb1 = *(const float4*)(Wb + (size_t)(bk + 8) * N + bc);

    As[ac+0][ar]    = va0.x; As[ac+1][ar]    = va0.y; As[ac+2][ar]    = va0.z; As[ac+3][ar]    = va0.w;
    As[ac+0][ar+64] = va1.x; As[ac+1][ar+64] = va1.y; As[ac+2][ar+64] = va1.z; As[ac+3][ar+64] = va1.w;
    *(float4*)&Bs[bk][bc]     = vb0;
    *(float4*)&Bs[bk + 8][bc] = vb1;
    __syncthreads();

    const int KT = K >> 4;
    for (int kt = 0; kt < KT; kt++) {
        if (kt + 1 < KT) {   // register prefetch of next tile
            const float* Ap = Ab + (kt + 1) * 16;
            const float* Wp = Wb + (size_t)((kt + 1) * 16) * N;
            va0 = *(const float4*)(Ap + (size_t)ar * K + ac);
            va1 = *(const float4*)(Ap + (size_t)(ar + 64) * K + ac);
            vb0 = *(const float4*)(Wp + (size_t)bk * N + bc);
            vb1 = *(const float4*)(Wp + (size_t)(bk + 8) * N + bc);
        }
        #pragma unroll
        for (int k = 0; k < 16; k++) {
            float4 a0 = *(const float4*)&As[k][ty * 8];
            float4 a1 = *(const float4*)&As[k][ty * 8 + 4];
            ulonglong2 b0 = *(const ulonglong2*)&Bs[k][tx * 8];
            ulonglong2 b1 = *(const ulonglong2*)&Bs[k][tx * 8 + 4];
            const u64 bp0 = b0.x, bp1 = b0.y, bp2 = b1.x, bp3 = b1.y;
            float af[8] = {a0.x, a0.y, a0.z, a0.w, a1.x, a1.y, a1.z, a1.w};
            #pragma unroll
            for (int i = 0; i < 8; i++) {
                u64 ap = pk2(af[i], af[i]);
                acc[i][0] = fma2(ap, bp0, acc[i][0]);
                acc[i][1] = fma2(ap, bp1, acc[i][1]);
                acc[i][2] = fma2(ap, bp2, acc[i][2]);
                acc[i][3] = fma2(ap, bp3, acc[i][3]);
            }
        }
        if (kt + 1 < KT) {
            __syncthreads();
            As[ac+0][ar]    = va0.x; As[ac+1][ar]    = va0.y; As[ac+2][ar]    = va0.z; As[ac+3][ar]    = va0.w;
            As[ac+0][ar+64] = va1.x; As[ac+1][ar+64] = va1.y; As[ac+2][ar+64] = va1.z; As[ac+3][ar+64] = va1.w;
            *(float4*)&Bs[bk][bc]     = vb0;
            *(float4*)&Bs[bk + 8][bc] = vb1;
            __syncthreads();
        }
    }

    // epilogue (+ optional RoPE)
    #pragma unroll
    for (int i = 0; i < 8; i++) {
        const int r = row0 + ty * 8 + i;
        float out[8];
        #pragma unroll
        for (int j = 0; j < 4; j++) upk2(acc[i][j], out[2 * j], out[2 * j + 1]);
        if (ROPE) {
            const int t     = r & (T_SZ - 1);
            const int cbase = col0 + tx * 8;
            #pragma unroll
            for (int j = 0; j < 8; j += 2) {
                const int d = (cbase + j) & (HDIM - 1);
                const int p = d >> 1;
                const float cz = fc[t * (HDIM / 2) + p];
                const float sz = fs[t * (HDIM / 2) + p];
                const float xr = out[j], xi = out[j + 1];
                out[j]     = xr * cz - xi * sz;
                out[j + 1] = xr * sz + xi * cz;
            }
        }
        float4* dst = (float4*)(C + (size_t)r * N + col0 + tx * 8);
        dst[0] = make_float4(out[0], out[1], out[2], out[3]);
        dst[1] = make_float4(out[4], out[5], out[6], out[7]);
    }
}

// =====================================================================
// Flash attention (fp32, online softmax). 64 q-rows x 64 k-cols per tile,
// HD=128. 256 threads: S is 4x4/thread (ty->rows, tx->cols), O is
// 4 rows x 8 cols/thread (f32x2 packed pairs along columns).
// Causal mask via -1e30 sentinel; GQA kvh = h/4; scale folded into Q.
// =====================================================================
#define FPD 132                      // 128 + 4 padding (floats)
#define FLASH_SMEM_BYTES ((3*64*FPD + 64*68 + 64*17 + 3*64) * 4)

__global__ __launch_bounds__(256, 1)
void flash_kernel(const float* __restrict__ Qg, const float* __restrict__ Kg,
                  const float* __restrict__ Vg, float* __restrict__ Og)
{
    extern __shared__ float sh[];
    float (*Qs)[FPD] = reinterpret_cast<float(*)[FPD]>(sh);
    float (*Ks)[FPD] = reinterpret_cast<float(*)[FPD]>(sh + 64 * FPD);
    float (*Vs)[FPD] = reinterpret_cast<float(*)[FPD]>(sh + 2 * 64 * FPD);
    float (*Ps)[68]  = reinterpret_cast<float(*)[68]> (sh + 3 * 64 * FPD);
    float (*red)[17] = reinterpret_cast<float(*)[17]> (sh + 3 * 64 * FPD + 64 * 68);
    float* sm_m = sh + 3 * 64 * FPD + 64 * 68 + 64 * 17;
    float* sm_l = sm_m + 64;
    float* sm_a = sm_l + 64;

    const int tid = threadIdx.x;
    const int tx  = tid & 15;
    const int ty  = tid >> 4;
    const int qt  = blockIdx.x;
    const int bh  = blockIdx.y;
    const int b   = bh >> 4;
    const int h   = bh & 15;
    const int kvh = h >> 2;                 // N_GROUP = 4 (jnp.repeat)
    const int qrow0 = b * T_SZ + qt * 64;
    const float scale = 0.08838834764831845f;   // 1/sqrt(128)

    // load Q tile (scale folded in)
    #pragma unroll
    for (int s = 0; s < 8; s++) {
        const int u = tid + s * 256;
        const int r = u >> 5, c4 = (u & 31) << 2;
        float4 v = *(const float4*)(Qg + (size_t)(qrow0 + r) * DIM_ + h * HDIM + c4);
        v.x *= scale; v.y *= scale; v.z *= scale; v.w *= scale;
        *(float4*)&Qs[r][c4] = v;
    }
    if (tid < 64) { sm_m[tid] = -1e30f; sm_l[tid] = 0.f; }

    u64 accO[4][4];
    #pragma unroll
    for (int i = 0; i < 4; i++)
        #pragma unroll
        for (int j = 0; j < 4; j++) accO[i][j] = 0ull;
    __syncthreads();

    for (int kt = 0; kt <= qt; kt++) {
        const int krow0 = b * T_SZ + kt * 64;
        #pragma unroll
        for (int s = 0; s < 8; s++) {
            const int u = tid + s * 256;
            const int r = u >> 5, c4 = (u & 31) << 2;
            *(float4*)&Ks[r][c4] =
                *(const float4*)(Kg + (size_t)(krow0 + r) * KVDIM + kvh * HDIM + c4);
        }
        #pragma unroll
        for (int s = 0; s < 8; s++) {
            const int u = tid + s * 256;
            const int r = u >> 5, c4 = (u & 31) << 2;
            *(float4*)&Vs[r][c4] =
                *(const float4*)(Vg + (size_t)(krow0 + r) * KVDIM + kvh * HDIM + c4);
        }
        __syncthreads();

        // --- S = Qs * Ks^T (packed along d; lo=even d, hi=odd d) ---
        u64 s2[4][4];
        #pragma unroll
        for (int i = 0; i < 4; i++)
            #pragma unroll
            for (int j = 0; j < 4; j++) s2[i][j] = 0ull;
        #pragma unroll 4
        for (int dd = 0; dd < HDIM; dd += 4) {
            ulonglong2 q2[4], k2[4];
            #pragma unroll
            for (int i = 0; i < 4; i++) q2[i] = *(const ulonglong2*)&Qs[ty * 4 + i][dd];
            #pragma unroll
            for (int j = 0; j < 4; j++) k2[j] = *(const ulonglong2*)&Ks[tx * 4 + j][dd];
            #pragma unroll
            for (int i = 0; i < 4; i++)
                #pragma unroll
                for (int j = 0; j < 4; j++) {
                    s2[i][j] = fma2(q2[i].x, k2[j].x, s2[i][j]);
                    s2[i][j] = fma2(q2[i].y, k2[j].y, s2[i][j]);
                }
        }
        float sv[4][4];
        #pragma unroll
        for (int i = 0; i < 4; i++)
            #pragma unroll
            for (int j = 0; j < 4; j++) {
                float lo, hi; upk2(s2[i][j], lo, hi); sv[i][j] = lo + hi;
            }
        if (kt == qt) {   // causal mask on diagonal tile
            #pragma unroll
            for (int i = 0; i < 4; i++)
                #pragma unroll
                for (int j = 0; j < 4; j++)
                    if (tx * 4 + j > ty * 4 + i) sv[i][j] = -1e30f;
        }

        // --- row max (partial per thread, reduce over tx) ---
        #pragma unroll
        for (int i = 0; i < 4; i++) {
            float m = fmaxf(fmaxf(sv[i][0], sv[i][1]), fmaxf(sv[i][2], sv[i][3]));
            red[ty * 4 + i][tx] = m;
        }
        __syncthreads();
        if (tid < 64) {
            float m = red[tid][0];
            #pragma unroll
            for (int x = 1; x < 16; x++) m = fmaxf(m, red[tid][x]);
            const float mp = sm_m[tid];
            const float mn = fmaxf(mp, m);
            sm_a[tid] = __expf(mp - mn);   // underflows to 0 on first tile
            sm_m[tid] = mn;
        }
        __syncthreads();

        // --- P = exp(S - m), partial row sums ---
        #pragma unroll
        for (int i = 0; i < 4; i++) {
            const int r = ty * 4 + i;
            const float mn = sm_m[r];
            float rs = 0.f;
            #pragma unroll
            for (int j = 0; j < 4; j++) {
                const float p = __expf(sv[i][j] - mn);
                Ps[r][tx * 4 + j] = p;
                rs += p;
            }
            red[r][tx] = rs;
        }
        __syncthreads();
        if (tid < 64) {
            float s = 0.f;
            #pragma unroll
            for (int x = 0; x < 16; x++) s += red[tid][x];
            sm_l[tid] = sm_l[tid] * sm_a[tid] + s;
        }

        // --- rescale O by alpha, then O += P @ V (packed along cols) ---
        #pragma unroll
        for (int i = 0; i < 4; i++) {
            const float a = sm_a[ty * 4 + i];
            const u64 aa = pk2(a, a);
            #pragma unroll
            for (int jp = 0; jp < 4; jp++) accO[i][jp] = mul2(accO[i][jp], aa);
        }
        #pragma unroll 4
        for (int kk = 0; kk < 64; kk++) {
            ulonglong2 v0 = *(const ulonglong2*)&Vs[kk][tx * 8];
            ulonglong2 v1 = *(const ulonglong2*)&Vs[kk][tx * 8 + 4];
            const u64 vp0 = v0.x, vp1 = v0.y, vp2 = v1.x, vp3 = v1.y;
            #pragma unroll
            for (int i = 0; i < 4; i++) {
                const float p = Ps[ty * 4 + i][kk];
                const u64 pp = pk2(p, p);
                accO[i][0] = fma2(pp, vp0, accO[i][0]);
                accO[i][1] = fma2(pp, vp1, accO[i][1]);
                accO[i][2] = fma2(pp, vp2, accO[i][2]);
                accO[i][3] = fma2(pp, vp3, accO[i][3]);
            }
        }
        __syncthreads();   // protect K/V/Ps/red before next iteration
    }

    // normalize and write
    #pragma unroll
    for (int i = 0; i < 4; i++) {
        const int r = ty * 4 + i;
        const float inv = 1.f / sm_l[r];
        float o[8];
        #pragma unroll
        for (int jp = 0; jp < 4; jp++) upk2(accO[i][jp], o[2 * jp], o[2 * jp + 1]);
        #pragma unroll
        for (int c = 0; c < 8; c++) o[c] *= inv;
        float4* dst = (float4*)(Og + (size_t)(qrow0 + r) * DIM_ + h * HDIM + tx * 8);
        dst[0] = make_float4(o[0], o[1], o[2], o[3]);
        dst[1] = make_float4(o[4], o[5], o[6], o[7]);
    }
}

// =====================================================================
// launch
// =====================================================================
extern "C" void kernel_launch(void* const* d_in, const int* in_sizes, int n_in,
                              void* d_out, int out_size)
{
    const float* x  = (const float*)d_in[0];
    const float* fc = (const float*)d_in[1];
    const float* fs = (const float*)d_in[2];
    const float* wq = (const float*)d_in[3];
    const float* wk = (const float*)d_in[4];
    const float* wv = (const float*)d_in[5];
    const float* wo = (const float*)d_in[6];
    float* out = (float*)d_out;

    float *q, *k, *v, *att;
    cudaGetSymbolAddress((void**)&q,   g_q);
    cudaGetSymbolAddress((void**)&k,   g_k);
    cudaGetSymbolAddress((void**)&v,   g_v);
    cudaGetSymbolAddress((void**)&att, g_att);

    cudaFuncSetAttribute(flash_kernel, cudaFuncAttributeMaxDynamicSharedMemorySize,
                         FLASH_SMEM_BYTES);

    dim3 blk(256);
    // Q = rope(x @ wq), K = rope(x @ wk), V = x @ wv
    sgemm_kernel<true ><<<dim3(DIM_  / 128, MROWS / 128), blk>>>(x, wq, q, DIM_,  DIM_, fc, fs);
    sgemm_kernel<true ><<<dim3(KVDIM / 128, MROWS / 128), blk>>>(x, wk, k, KVDIM, DIM_, fc, fs);
    sgemm_kernel<false><<<dim3(KVDIM / 128, MROWS / 128), blk>>>(x, wv, v, KVDIM, DIM_, nullptr, nullptr);
    // attention
    flash_kernel<<<dim3(T_SZ / 64, B_SZ * NHEAD), blk, FLASH_SMEM_BYTES>>>(q, k, v, att);
    // out = att @ wo
    sgemm_kernel<false><<<dim3(DIM_ / 128, MROWS / 128), blk>>>(att, wo, out, DIM_, DIM_, nullptr, nullptr);
}

// round 8
// speedup vs baseline: 1.3350x; 1.3350x over previous
#include <cuda_runtime.h>
#include <cuda_bf16.h>
#include <cstdint>

typedef unsigned long long u64;

#define B_SZ   2
#define T_SZ   2048
#define DIM_   2048
#define NHEAD  16
#define KVHEAD 4
#define HDIM   128
#define MROWS  (B_SZ * T_SZ)        // 4096
#define KVDIM  (KVHEAD * HDIM)      // 512
#define GK     2048                  // shared K of all projections

// ================= scratch (device globals; no allocations allowed) =========
__device__ float g_q[(size_t)MROWS * DIM_];
__device__ float g_k[(size_t)MROWS * KVDIM];
__device__ float g_v[(size_t)MROWS * KVDIM];
__device__ float g_att[(size_t)MROWS * DIM_];

__device__ __align__(16) __nv_bfloat16 g_xh[(size_t)MROWS * DIM_];
__device__ __align__(16) __nv_bfloat16 g_xl[(size_t)MROWS * DIM_];
__device__ __align__(16) __nv_bfloat16 g_wqth[(size_t)DIM_ * DIM_];   // [N,K]
__device__ __align__(16) __nv_bfloat16 g_wqtl[(size_t)DIM_ * DIM_];
__device__ __align__(16) __nv_bfloat16 g_wkth[(size_t)KVDIM * DIM_];
__device__ __align__(16) __nv_bfloat16 g_wktl[(size_t)KVDIM * DIM_];
__device__ __align__(16) __nv_bfloat16 g_wvth[(size_t)KVDIM * DIM_];
__device__ __align__(16) __nv_bfloat16 g_wvtl[(size_t)KVDIM * DIM_];
__device__ __align__(16) __nv_bfloat16 g_woth[(size_t)DIM_ * DIM_];
__device__ __align__(16) __nv_bfloat16 g_wotl[(size_t)DIM_ * DIM_];
__device__ __align__(16) __nv_bfloat16 g_ath[(size_t)MROWS * DIM_];
__device__ __align__(16) __nv_bfloat16 g_atl[(size_t)MROWS * DIM_];

// ================= helpers ===================================================
__device__ __forceinline__ uint32_t smem_u32(const void* p) {
    uint32_t a;
    asm("{ .reg .u64 t; cvta.to.shared.u64 t, %1; cvt.u32.u64 %0, t; }" : "=r"(a) : "l"(p));
    return a;
}
__device__ __forceinline__ void ldsm4(uint32_t (&r)[4], uint32_t addr) {
    asm volatile("ldmatrix.sync.aligned.m8n8.x4.shared.b16 {%0,%1,%2,%3}, [%4];"
                 : "=r"(r[0]), "=r"(r[1]), "=r"(r[2]), "=r"(r[3]) : "r"(addr));
}
__device__ __forceinline__ void mma16816(float (&d)[4], const uint32_t (&a)[4],
                                         uint32_t b0, uint32_t b1) {
    asm volatile("mma.sync.aligned.m16n8k16.row.col.f32.bf16.bf16.f32 "
                 "{%0,%1,%2,%3}, {%4,%5,%6,%7}, {%8,%9}, {%0,%1,%2,%3};"
                 : "+f"(d[0]), "+f"(d[1]), "+f"(d[2]), "+f"(d[3])
                 : "r"(a[0]), "r"(a[1]), "r"(a[2]), "r"(a[3]), "r"(b0), "r"(b1));
}
#define CP_ASYNC16(sm, gm) \
    asm volatile("cp.async.cg.shared.global [%0], [%1], 16;" :: "r"(sm), "l"(gm) : "memory")
#define CP_COMMIT() asm volatile("cp.async.commit_group;" ::: "memory")
#define CP_WAIT(n)  asm volatile("cp.async.wait_group %0;" :: "n"(n) : "memory")

// ================= split / transpose-split conversion kernels ================
__global__ void split_kernel(const float* __restrict__ in, __nv_bfloat16* __restrict__ hi,
                             __nv_bfloat16* __restrict__ lo, int n4)
{
    int i = blockIdx.x * 256 + threadIdx.x;
    if (i >= n4) return;
    float4 v = ((const float4*)in)[i];
    float f[4] = {v.x, v.y, v.z, v.w};
    __nv_bfloat16 h[4], l[4];
    #pragma unroll
    for (int j = 0; j < 4; j++) {
        h[j] = __float2bfloat16(f[j]);
        l[j] = __float2bfloat16(f[j] - __bfloat162float(h[j]));
    }
    __nv_bfloat162 p0, p1, q0, q1;
    p0.x = h[0]; p0.y = h[1]; p1.x = h[2]; p1.y = h[3];
    q0.x = l[0]; q0.y = l[1]; q1.x = l[2]; q1.y = l[3];
    ((__nv_bfloat162*)hi)[2 * i]     = p0;
    ((__nv_bfloat162*)hi)[2 * i + 1] = p1;
    ((__nv_bfloat162*)lo)[2 * i]     = q0;
    ((__nv_bfloat162*)lo)[2 * i + 1] = q1;
}

// in: [R,C] fp32 row-major  ->  out hi/lo: [C,R] bf16 row-major (transposed)
__global__ void tsplit_kernel(const float* __restrict__ in, __nv_bfloat16* __restrict__ hi,
                              __nv_bfloat16* __restrict__ lo, int R, int C)
{
    __shared__ float tile[32][33];
    const int bx = blockIdx.x << 5;   // C offset
    const int by = blockIdx.y << 5;   // R offset
    const int tx = threadIdx.x & 31, ty = threadIdx.x >> 5;
    #pragma unroll
    for (int r = ty; r < 32; r += 8)
        tile[r][tx] = in[(size_t)(by + r) * C + bx + tx];
    __syncthreads();
    #pragma unroll
    for (int r = ty; r < 32; r += 8) {
        float v = tile[tx][r];
        __nv_bfloat16 h = __float2bfloat16(v);
        __nv_bfloat16 l = __float2bfloat16(v - __bfloat162float(h));
        size_t o = (size_t)(bx + r) * R + by + tx;
        hi[o] = h; lo[o] = l;
    }
}

// ================= split-bf16 HMMA GEMM ======================================
// C[M,N] = A[M,K] @ B^T, A=[M,K] hi/lo, B=[N,K] hi/lo. CTA 128x128, BK=32,
// 8 warps (4x2), warp tile 32x64, m16n8k16 mma, 2-stage cp.async pipeline.
// 3-pass: Ah*Bh + Ah*Bl + Al*Bh (fp32 accum in registers).
#define BK        32
#define NKB       (GK / BK)          // 64
#define TPITCH    80                 // 32 bf16 = 64B + 16B pad (ldmatrix conflict-free)
#define TILE_BY   (128 * TPITCH)     // 10240
#define SOFF_AH   0
#define SOFF_AL   (1 * TILE_BY)
#define SOFF_BH   (2 * TILE_BY)
#define SOFF_BL   (3 * TILE_BY)
#define STAGE_BY  (4 * TILE_BY)      // 40960
#define GEMM_SMEM (2 * STAGE_BY)     // 81920

__device__ __forceinline__ void load_stage(
    const __nv_bfloat16* __restrict__ Abh, const __nv_bfloat16* __restrict__ Abl,
    const __nv_bfloat16* __restrict__ Bbh, const __nv_bfloat16* __restrict__ Bbl,
    int kof, uint32_t sbuf, int tid)
{
    #pragma unroll
    for (int i = 0; i < 2; i++) {
        const int c   = tid + (i << 8);            // 0..511
        const int row = c >> 2, q = c & 3;
        const size_t   go = (size_t)row * GK + kof + q * 8;
        const uint32_t so = row * TPITCH + q * 16;
        CP_ASYNC16(sbuf + SOFF_AH + so, Abh + go);
        CP_ASYNC16(sbuf + SOFF_AL + so, Abl + go);
        CP_ASYNC16(sbuf + SOFF_BH + so, Bbh + go);
        CP_ASYNC16(sbuf + SOFF_BL + so, Bbl + go);
    }
}

template<bool ROPE>
__global__ __launch_bounds__(256, 1)
void mma_gemm_kernel(const __nv_bfloat16* __restrict__ Ah, const __nv_bfloat16* __restrict__ Al,
                     const __nv_bfloat16* __restrict__ Bh, const __nv_bfloat16* __restrict__ Bl,
                     float* __restrict__ C, int N,
                     const float* __restrict__ fc, const float* __restrict__ fs)
{
    extern __shared__ char smem[];
    const uint32_t sbase = smem_u32(smem);
    const int tid  = threadIdx.x;
    const int lane = tid & 31, wid = tid >> 5;
    const int wm   = wid & 3,  wn  = wid >> 2;       // 4 x 2 warp grid
    const int row0 = blockIdx.y << 7, col0 = blockIdx.x << 7;

    const __nv_bfloat16* Abh = Ah + (size_t)row0 * GK;
    const __nv_bfloat16* Abl = Al + (size_t)row0 * GK;
    const __nv_bfloat16* Bbh = Bh + (size_t)col0 * GK;
    const __nv_bfloat16* Bbl = Bl + (size_t)col0 * GK;

    float acc[2][8][4];
    #pragma unroll
    for (int mi = 0; mi < 2; mi++)
        #pragma unroll
        for (int ni = 0; ni < 8; ni++)
            #pragma unroll
            for (int e = 0; e < 4; e++) acc[mi][ni][e] = 0.f;

    // ldmatrix per-lane address components (within a tile)
    const uint32_t a_row = wm * 32 + (lane & 15);
    const uint32_t a_col = (lane >> 4) << 4;                 // +16B for k8-15
    const uint32_t b_rowb = wn * 64 + (lane & 7) + ((lane >> 4) << 3);
    const uint32_t b_col  = ((lane >> 3) & 1) << 4;

    load_stage(Abh, Abl, Bbh, Bbl, 0, sbase, tid);
    CP_COMMIT();

    for (int blk = 0; blk < NKB; blk++) {
        const uint32_t buf = sbase + (uint32_t)(blk & 1) * STAGE_BY;
        if (blk + 1 < NKB) {
            load_stage(Abh, Abl, Bbh, Bbl, (blk + 1) * BK,
                       sbase + (uint32_t)((blk + 1) & 1) * STAGE_BY, tid);
            CP_COMMIT();
            CP_WAIT(1);
        } else {
            CP_WAIT(0);
        }
        __syncthreads();

        #pragma unroll
        for (int ks = 0; ks < 2; ks++) {
            const uint32_t koff = ks * 32;   // 16 bf16 = 32B
            uint32_t ah[2][4], al[2][4];
            #pragma unroll
            for (int mi = 0; mi < 2; mi++) {
                const uint32_t aaddr = buf + SOFF_AH + (a_row + mi * 16) * TPITCH + koff + a_col;
                ldsm4(ah[mi], aaddr);
                ldsm4(al[mi], aaddr + (SOFF_AL - SOFF_AH));
            }
            uint32_t bh[4][4], bl[4][4];
            #pragma unroll
            for (int nq = 0; nq < 4; nq++) {
                const uint32_t baddr = buf + SOFF_BH + (b_rowb + nq * 16) * TPITCH + koff + b_col;
                ldsm4(bh[nq], baddr);
                ldsm4(bl[nq], baddr + (SOFF_BL - SOFF_BH));
            }
            #pragma unroll
            for (int mi = 0; mi < 2; mi++)
                #pragma unroll
                for (int nq = 0; nq < 4; nq++)
                    #pragma unroll
                    for (int hf = 0; hf < 2; hf++) {
                        const int ni = nq * 2 + hf;
                        const uint32_t b0h = bh[nq][hf * 2], b1h = bh[nq][hf * 2 + 1];
                        const uint32_t b0l = bl[nq][hf * 2], b1l = bl[nq][hf * 2 + 1];
                        mma16816(acc[mi][ni], ah[mi], b0h, b1h);
                        mma16816(acc[mi][ni], ah[mi], b0l, b1l);
                        mma16816(acc[mi][ni], al[mi], b0h, b1h);
                    }
        }
        __syncthreads();
    }

    // epilogue (+ optional fused RoPE)
    const int lr = lane >> 2;            // 0..7
    const int lc = (lane & 3) << 1;      // even col within atom
    #pragma unroll
    for (int mi = 0; mi < 2; mi++) {
        #pragma unroll
        for (int ni = 0; ni < 8; ni++) {
            float* d = acc[mi][ni];
            const int r0  = row0 + wm * 32 + mi * 16 + lr;
            const int r1  = r0 + 8;
            const int col = col0 + wn * 64 + ni * 8 + lc;
            if (ROPE) {
                const int p = (col & (HDIM - 1)) >> 1;
                {
                    const int t = r0 & (T_SZ - 1);
                    const float cz = fc[t * (HDIM / 2) + p];
                    const float sz = fs[t * (HDIM / 2) + p];
                    const float xr = d[0], xi = d[1];
                    d[0] = xr * cz - xi * sz;
                    d[1] = xr * sz + xi * cz;
                }
                {
                    const int t = r1 & (T_SZ - 1);
                    const float cz = fc[t * (HDIM / 2) + p];
                    const float sz = fs[t * (HDIM / 2) + p];
                    const float xr = d[2], xi = d[3];
                    d[2] = xr * cz - xi * sz;
                    d[3] = xr * sz + xi * cz;
                }
            }
            *(float2*)(C + (size_t)r0 * N + col) = make_float2(d[0], d[1]);
            *(float2*)(C + (size_t)r1 * N + col) = make_float2(d[2], d[3]);
        }
    }
}

// ================= flash attention (fp32, unchanged from passing R6) =========
__device__ __forceinline__ u64 pk2(float lo, float hi) {
    u64 r; asm("mov.b64 %0, {%1,%2};" : "=l"(r) : "f"(lo), "f"(hi)); return r;
}
__device__ __forceinline__ void upk2(u64 v, float& lo, float& hi) {
    asm("mov.b64 {%0,%1}, %2;" : "=f"(lo), "=f"(hi) : "l"(v));
}
__device__ __forceinline__ u64 fma2(u64 a, u64 b, u64 c) {
    u64 d; asm("fma.rn.f32x2 %0, %1, %2, %3;" : "=l"(d) : "l"(a), "l"(b), "l"(c)); return d;
}
__device__ __forceinline__ u64 mul2(u64 a, u64 b) {
    u64 d; asm("mul.rn.f32x2 %0, %1, %2;" : "=l"(d) : "l"(a), "l"(b)); return d;
}

#define FPD 132
#define FLASH_SMEM_BYTES ((3*64*FPD + 64*68 + 64*17 + 3*64) * 4)

__global__ __launch_bounds__(256, 1)
void flash_kernel(const float* __restrict__ Qg, const float* __restrict__ Kg,
                  const float* __restrict__ Vg, float* __restrict__ Og)
{
    extern __shared__ float sh[];
    float (*Qs)[FPD] = reinterpret_cast<float(*)[FPD]>(sh);
    float (*Ks)[FPD] = reinterpret_cast<float(*)[FPD]>(sh + 64 * FPD);
    float (*Vs)[FPD] = reinterpret_cast<float(*)[FPD]>(sh + 2 * 64 * FPD);
    float (*Ps)[68]  = reinterpret_cast<float(*)[68]> (sh + 3 * 64 * FPD);
    float (*red)[17] = reinterpret_cast<float(*)[17]> (sh + 3 * 64 * FPD + 64 * 68);
    float* sm_m = sh + 3 * 64 * FPD + 64 * 68 + 64 * 17;
    float* sm_l = sm_m + 64;
    float* sm_a = sm_l + 64;

    const int tid = threadIdx.x;
    const int tx  = tid & 15;
    const int ty  = tid >> 4;
    const int qt  = blockIdx.x;
    const int bh  = blockIdx.y;
    const int b   = bh >> 4;
    const int h   = bh & 15;
    const int kvh = h >> 2;
    const int qrow0 = b * T_SZ + qt * 64;
    const float scale = 0.08838834764831845f;

    #pragma unroll
    for (int s = 0; s < 8; s++) {
        const int u = tid + s * 256;
        const int r = u >> 5, c4 = (u & 31) << 2;
        float4 v = *(const float4*)(Qg + (size_t)(qrow0 + r) * DIM_ + h * HDIM + c4);
        v.x *= scale; v.y *= scale; v.z *= scale; v.w *= scale;
        *(float4*)&Qs[r][c4] = v;
    }
    if (tid < 64) { sm_m[tid] = -1e30f; sm_l[tid] = 0.f; }

    u64 accO[4][4];
    #pragma unroll
    for (int i = 0; i < 4; i++)
        #pragma unroll
        for (int j = 0; j < 4; j++) accO[i][j] = 0ull;
    __syncthreads();

    for (int kt = 0; kt <= qt; kt++) {
        const int krow0 = b * T_SZ + kt * 64;
        #pragma unroll
        for (int s = 0; s < 8; s++) {
            const int u = tid + s * 256;
            const int r = u >> 5, c4 = (u & 31) << 2;
            *(float4*)&Ks[r][c4] =
                *(const float4*)(Kg + (size_t)(krow0 + r) * KVDIM + kvh * HDIM + c4);
        }
        #pragma unroll
        for (int s = 0; s < 8; s++) {
            const int u = tid + s * 256;
            const int r = u >> 5, c4 = (u & 31) << 2;
            *(float4*)&Vs[r][c4] =
                *(const float4*)(Vg + (size_t)(krow0 + r) * KVDIM + kvh * HDIM + c4);
        }
        __syncthreads();

        u64 s2[4][4];
        #pragma unroll
        for (int i = 0; i < 4; i++)
            #pragma unroll
            for (int j = 0; j < 4; j++) s2[i][j] = 0ull;
        #pragma unroll 4
        for (int dd = 0; dd < HDIM; dd += 4) {
            ulonglong2 q2[4], k2[4];
            #pragma unroll
            for (int i = 0; i < 4; i++) q2[i] = *(const ulonglong2*)&Qs[ty * 4 + i][dd];
            #pragma unroll
            for (int j = 0; j < 4; j++) k2[j] = *(const ulonglong2*)&Ks[tx * 4 + j][dd];
            #pragma unroll
            for (int i = 0; i < 4; i++)
                #pragma unroll
                for (int j = 0; j < 4; j++) {
                    s2[i][j] = fma2(q2[i].x, k2[j].x, s2[i][j]);
                    s2[i][j] = fma2(q2[i].y, k2[j].y, s2[i][j]);
                }
        }
        float sv[4][4];
        #pragma unroll
        for (int i = 0; i < 4; i++)
            #pragma unroll
            for (int j = 0; j < 4; j++) {
                float lo, hi; upk2(s2[i][j], lo, hi); sv[i][j] = lo + hi;
            }
        if (kt == qt) {
            #pragma unroll
            for (int i = 0; i < 4; i++)
                #pragma unroll
                for (int j = 0; j < 4; j++)
                    if (tx * 4 + j > ty * 4 + i) sv[i][j] = -1e30f;
        }

        #pragma unroll
        for (int i = 0; i < 4; i++) {
            float m = fmaxf(fmaxf(sv[i][0], sv[i][1]), fmaxf(sv[i][2], sv[i][3]));
            red[ty * 4 + i][tx] = m;
        }
        __syncthreads();
        if (tid < 64) {
            float m = red[tid][0];
            #pragma unroll
            for (int x = 1; x < 16; x++) m = fmaxf(m, red[tid][x]);
            const float mp = sm_m[tid];
            const float mn = fmaxf(mp, m);
            sm_a[tid] = __expf(mp - mn);
            sm_m[tid] = mn;
        }
        __syncthreads();

        #pragma unroll
        for (int i = 0; i < 4; i++) {
            const int r = ty * 4 + i;
            const float mn = sm_m[r];
            float rs = 0.f;
            #pragma unroll
            for (int j = 0; j < 4; j++) {
                const float p = __expf(sv[i][j] - mn);
                Ps[r][tx * 4 + j] = p;
                rs += p;
            }
            red[r][tx] = rs;
        }
        __syncthreads();
        if (tid < 64) {
            float s = 0.f;
            #pragma unroll
            for (int x = 0; x < 16; x++) s += red[tid][x];
            sm_l[tid] = sm_l[tid] * sm_a[tid] + s;
        }

        #pragma unroll
        for (int i = 0; i < 4; i++) {
            const float a = sm_a[ty * 4 + i];
            const u64 aa = pk2(a, a);
            #pragma unroll
            for (int jp = 0; jp < 4; jp++) accO[i][jp] = mul2(accO[i][jp], aa);
        }
        #pragma unroll 4
        for (int kk = 0; kk < 64; kk++) {
            ulonglong2 v0 = *(const ulonglong2*)&Vs[kk][tx * 8];
            ulonglong2 v1 = *(const ulonglong2*)&Vs[kk][tx * 8 + 4];
            const u64 vp0 = v0.x, vp1 = v0.y, vp2 = v1.x, vp3 = v1.y;
            #pragma unroll
            for (int i = 0; i < 4; i++) {
                const float p = Ps[ty * 4 + i][kk];
                const u64 pp = pk2(p, p);
                accO[i][0] = fma2(pp, vp0, accO[i][0]);
                accO[i][1] = fma2(pp, vp1, accO[i][1]);
                accO[i][2] = fma2(pp, vp2, accO[i][2]);
                accO[i][3] = fma2(pp, vp3, accO[i][3]);
            }
        }
        __syncthreads();
    }

    #pragma unroll
    for (int i = 0; i < 4; i++) {
        const int r = ty * 4 + i;
        const float inv = 1.f / sm_l[r];
        float o[8];
        #pragma unroll
        for (int jp = 0; jp < 4; jp++) upk2(accO[i][jp], o[2 * jp], o[2 * jp + 1]);
        #pragma unroll
        for (int c = 0; c < 8; c++) o[c] *= inv;
        float4* dst = (float4*)(Og + (size_t)(qrow0 + r) * DIM_ + h * HDIM + tx * 8);
        dst[0] = make_float4(o[0], o[1], o[2], o[3]);
        dst[1] = make_float4(o[4], o[5], o[6], o[7]);
    }
}

// ================= launch ====================================================
extern "C" void kernel_launch(void* const* d_in, const int* in_sizes, int n_in,
                              void* d_out, int out_size)
{
    const float* x  = (const float*)d_in[0];
    const float* fc = (const float*)d_in[1];
    const float* fs = (const float*)d_in[2];
    const float* wq = (const float*)d_in[3];
    const float* wk = (const float*)d_in[4];
    const float* wv = (const float*)d_in[5];
    const float* wo = (const float*)d_in[6];
    float* out = (float*)d_out;

    float *q, *k, *v, *att;
    cudaGetSymbolAddress((void**)&q,   g_q);
    cudaGetSymbolAddress((void**)&k,   g_k);
    cudaGetSymbolAddress((void**)&v,   g_v);
    cudaGetSymbolAddress((void**)&att, g_att);
    __nv_bfloat16 *xh, *xl, *wqth, *wqtl, *wkth, *wktl, *wvth, *wvtl, *woth, *wotl, *ath, *atl;
    cudaGetSymbolAddress((void**)&xh,   g_xh);   cudaGetSymbolAddress((void**)&xl,   g_xl);
    cudaGetSymbolAddress((void**)&wqth, g_wqth); cudaGetSymbolAddress((void**)&wqtl, g_wqtl);
    cudaGetSymbolAddress((void**)&wkth, g_wkth); cudaGetSymbolAddress((void**)&wktl, g_wktl);
    cudaGetSymbolAddress((void**)&wvth, g_wvth); cudaGetSymbolAddress((void**)&wvtl, g_wvtl);
    cudaGetSymbolAddress((void**)&woth, g_woth); cudaGetSymbolAddress((void**)&wotl, g_wotl);
    cudaGetSymbolAddress((void**)&ath,  g_ath);  cudaGetSymbolAddress((void**)&atl,  g_atl);

    cudaFuncSetAttribute(flash_kernel, cudaFuncAttributeMaxDynamicSharedMemorySize,
                         FLASH_SMEM_BYTES);
    cudaFuncSetAttribute(mma_gemm_kernel<true>,  cudaFuncAttributeMaxDynamicSharedMemorySize,
                         GEMM_SMEM);
    cudaFuncSetAttribute(mma_gemm_kernel<false>, cudaFuncAttributeMaxDynamicSharedMemorySize,
                         GEMM_SMEM);

    const int n4x = MROWS * DIM_ / 4;
    split_kernel<<<n4x / 256, 256>>>(x, xh, xl, n4x);
    tsplit_kernel<<<dim3(DIM_  / 32, DIM_ / 32), 256>>>(wq, wqth, wqtl, DIM_, DIM_);
    tsplit_kernel<<<dim3(KVDIM / 32, DIM_ / 32), 256>>>(wk, wkth, wktl, DIM_, KVDIM);
    tsplit_kernel<<<dim3(KVDIM / 32, DIM_ / 32), 256>>>(wv, wvth, wvtl, DIM_, KVDIM);
    tsplit_kernel<<<dim3(DIM_  / 32, DIM_ / 32), 256>>>(wo, woth, wotl, DIM_, DIM_);

    mma_gemm_kernel<true ><<<dim3(DIM_  / 128, MROWS / 128), 256, GEMM_SMEM>>>(
        xh, xl, wqth, wqtl, q, DIM_,  fc, fs);
    mma_gemm_kernel<true ><<<dim3(KVDIM / 128, MROWS / 128), 256, GEMM_SMEM>>>(
        xh, xl, wkth, wktl, k, KVDIM, fc, fs);
    mma_gemm_kernel<false><<<dim3(KVDIM / 128, MROWS / 128), 256, GEMM_SMEM>>>(
        xh, xl, wvth, wvtl, v, KVDIM, nullptr, nullptr);

    flash_kernel<<<dim3(T_SZ / 64, B_SZ * NHEAD), 256, FLASH_SMEM_BYTES>>>(q, k, v, att);

    split_kernel<<<n4x / 256, 256>>>(att, ath, atl, n4x);
    mma_gemm_kernel<false><<<dim3(DIM_ / 128, MROWS / 128), 256, GEMM_SMEM>>>(
        ath, atl, woth, wotl, out, DIM_, nullptr, nullptr);
}

// round 9
// speedup vs baseline: 2.9178x; 2.1856x over previous
#include <cuda_runtime.h>
#include <cuda_bf16.h>
#include <cstdint>

#define B_SZ   2
#define T_SZ   2048
#define DIM_   2048
#define NHEAD  16
#define KVHEAD 4
#define HDIM   128
#define MROWS  (B_SZ * T_SZ)        // 4096
#define KVDIM  (KVHEAD * HDIM)      // 512
#define GK     2048

// ================= scratch (device globals; no allocations allowed) =========
__device__ float g_q[(size_t)MROWS * DIM_];
__device__ float g_k[(size_t)MROWS * KVDIM];
__device__ float g_v[(size_t)MROWS * KVDIM];
__device__ float g_att[(size_t)MROWS * DIM_];

__device__ __align__(16) __nv_bfloat16 g_xh[(size_t)MROWS * DIM_];
__device__ __align__(16) __nv_bfloat16 g_xl[(size_t)MROWS * DIM_];
__device__ __align__(16) __nv_bfloat16 g_wqth[(size_t)DIM_ * DIM_];   // [N,K]
__device__ __align__(16) __nv_bfloat16 g_wqtl[(size_t)DIM_ * DIM_];
__device__ __align__(16) __nv_bfloat16 g_wkth[(size_t)KVDIM * DIM_];
__device__ __align__(16) __nv_bfloat16 g_wktl[(size_t)KVDIM * DIM_];
__device__ __align__(16) __nv_bfloat16 g_wvth[(size_t)KVDIM * DIM_];
__device__ __align__(16) __nv_bfloat16 g_wvtl[(size_t)KVDIM * DIM_];
__device__ __align__(16) __nv_bfloat16 g_woth[(size_t)DIM_ * DIM_];
__device__ __align__(16) __nv_bfloat16 g_wotl[(size_t)DIM_ * DIM_];
__device__ __align__(16) __nv_bfloat16 g_ath[(size_t)MROWS * DIM_];
__device__ __align__(16) __nv_bfloat16 g_atl[(size_t)MROWS * DIM_];
// flash inputs (bf16 hi/lo)
__device__ __align__(16) __nv_bfloat16 g_qh[(size_t)MROWS * DIM_];
__device__ __align__(16) __nv_bfloat16 g_ql[(size_t)MROWS * DIM_];
__device__ __align__(16) __nv_bfloat16 g_kh[(size_t)MROWS * KVDIM];
__device__ __align__(16) __nv_bfloat16 g_kl[(size_t)MROWS * KVDIM];
__device__ __align__(16) __nv_bfloat16 g_vth[(size_t)B_SZ * KVDIM * T_SZ]; // [b*512+c][t]
__device__ __align__(16) __nv_bfloat16 g_vtl[(size_t)B_SZ * KVDIM * T_SZ];

// ================= helpers ===================================================
__device__ __forceinline__ uint32_t smem_u32(const void* p) {
    uint32_t a;
    asm("{ .reg .u64 t; cvta.to.shared.u64 t, %1; cvt.u32.u64 %0, t; }" : "=r"(a) : "l"(p));
    return a;
}
__device__ __forceinline__ void ldsm4(uint32_t (&r)[4], uint32_t addr) {
    asm volatile("ldmatrix.sync.aligned.m8n8.x4.shared.b16 {%0,%1,%2,%3}, [%4];"
                 : "=r"(r[0]), "=r"(r[1]), "=r"(r[2]), "=r"(r[3]) : "r"(addr));
}
__device__ __forceinline__ void mma16816(float (&d)[4], const uint32_t (&a)[4],
                                         uint32_t b0, uint32_t b1) {
    asm volatile("mma.sync.aligned.m16n8k16.row.col.f32.bf16.bf16.f32 "
                 "{%0,%1,%2,%3}, {%4,%5,%6,%7}, {%8,%9}, {%0,%1,%2,%3};"
                 : "+f"(d[0]), "+f"(d[1]), "+f"(d[2]), "+f"(d[3])
                 : "r"(a[0]), "r"(a[1]), "r"(a[2]), "r"(a[3]), "r"(b0), "r"(b1));
}
#define CP_ASYNC16(sm, gm) \
    asm volatile("cp.async.cg.shared.global [%0], [%1], 16;" :: "r"(sm), "l"(gm) : "memory")
#define CP_COMMIT() asm volatile("cp.async.commit_group;" ::: "memory")
#define CP_WAIT(n)  asm volatile("cp.async.wait_group %0;" :: "n"(n) : "memory")

__device__ __forceinline__ void split2(float a, float b, uint32_t& h, uint32_t& l) {
    __nv_bfloat16 ha = __float2bfloat16(a), hb = __float2bfloat16(b);
    float ra = a - __bfloat162float(ha), rb = b - __bfloat162float(hb);
    __nv_bfloat162 hp; hp.x = ha; hp.y = hb;
    __nv_bfloat162 lp; lp.x = __float2bfloat16(ra); lp.y = __float2bfloat16(rb);
    h = *reinterpret_cast<uint32_t*>(&hp);
    l = *reinterpret_cast<uint32_t*>(&lp);
}

// ================= split / transpose-split conversion kernels ================
__global__ void split_kernel(const float* __restrict__ in, __nv_bfloat16* __restrict__ hi,
                             __nv_bfloat16* __restrict__ lo, int n4, float scale)
{
    int i = blockIdx.x * 256 + threadIdx.x;
    if (i >= n4) return;
    float4 v = ((const float4*)in)[i];
    float f[4] = {v.x * scale, v.y * scale, v.z * scale, v.w * scale};
    uint32_t h0, l0, h1, l1;
    split2(f[0], f[1], h0, l0);
    split2(f[2], f[3], h1, l1);
    ((uint32_t*)hi)[2 * i]     = h0;
    ((uint32_t*)hi)[2 * i + 1] = h1;
    ((uint32_t*)lo)[2 * i]     = l0;
    ((uint32_t*)lo)[2 * i + 1] = l1;
}

// in: [R,C] fp32 row-major  ->  out hi/lo: [C,R] bf16 row-major (transposed)
__global__ void tsplit_kernel(const float* __restrict__ in, __nv_bfloat16* __restrict__ hi,
                              __nv_bfloat16* __restrict__ lo, int R, int C)
{
    __shared__ float tile[32][33];
    const int bx = blockIdx.x << 5;
    const int by = blockIdx.y << 5;
    const int tx = threadIdx.x & 31, ty = threadIdx.x >> 5;
    #pragma unroll
    for (int r = ty; r < 32; r += 8)
        tile[r][tx] = in[(size_t)(by + r) * C + bx + tx];
    __syncthreads();
    #pragma unroll
    for (int r = ty; r < 32; r += 8) {
        float v = tile[tx][r];
        __nv_bfloat16 h = __float2bfloat16(v);
        __nv_bfloat16 l = __float2bfloat16(v - __bfloat162float(h));
        size_t o = (size_t)(bx + r) * R + by + tx;
        hi[o] = h; lo[o] = l;
    }
}

// g_v [b*T + t][c] fp32 -> g_vt[(b*512 + c)][t] bf16 hi/lo (per-batch transpose)
__global__ void vtsplit_kernel(const float* __restrict__ in, __nv_bfloat16* __restrict__ hi,
                               __nv_bfloat16* __restrict__ lo)
{
    __shared__ float tile[32][33];
    const int t0 = blockIdx.x << 5;
    const int c0 = blockIdx.y << 5;
    const int b  = blockIdx.z;
    const int tx = threadIdx.x & 31, ty = threadIdx.x >> 5;
    #pragma unroll
    for (int r = ty; r < 32; r += 8)
        tile[r][tx] = in[(size_t)(b * T_SZ + t0 + r) * KVDIM + c0 + tx];
    __syncthreads();
    #pragma unroll
    for (int r = ty; r < 32; r += 8) {
        float v = tile[tx][r];
        __nv_bfloat16 h = __float2bfloat16(v);
        __nv_bfloat16 l = __float2bfloat16(v - __bfloat162float(h));
        size_t o = (size_t)(b * KVDIM + c0 + r) * T_SZ + t0 + tx;
        hi[o] = h; lo[o] = l;
    }
}

// ================= split-bf16 HMMA GEMM (unchanged from R8-passing) ==========
#define BK        32
#define NKB       (GK / BK)
#define TPITCH    80
#define TILE_BY   (128 * TPITCH)
#define SOFF_AH   0
#define SOFF_AL   (1 * TILE_BY)
#define SOFF_BH   (2 * TILE_BY)
#define SOFF_BL   (3 * TILE_BY)
#define STAGE_BY  (4 * TILE_BY)
#define GEMM_SMEM (2 * STAGE_BY)

__device__ __forceinline__ void load_stage(
    const __nv_bfloat16* __restrict__ Abh, const __nv_bfloat16* __restrict__ Abl,
    const __nv_bfloat16* __restrict__ Bbh, const __nv_bfloat16* __restrict__ Bbl,
    int kof, uint32_t sbuf, int tid)
{
    #pragma unroll
    for (int i = 0; i < 2; i++) {
        const int c   = tid + (i << 8);
        const int row = c >> 2, q = c & 3;
        const size_t   go = (size_t)row * GK + kof + q * 8;
        const uint32_t so = row * TPITCH + q * 16;
        CP_ASYNC16(sbuf + SOFF_AH + so, Abh + go);
        CP_ASYNC16(sbuf + SOFF_AL + so, Abl + go);
        CP_ASYNC16(sbuf + SOFF_BH + so, Bbh + go);
        CP_ASYNC16(sbuf + SOFF_BL + so, Bbl + go);
    }
}

template<bool ROPE>
__global__ __launch_bounds__(256, 1)
void mma_gemm_kernel(const __nv_bfloat16* __restrict__ Ah, const __nv_bfloat16* __restrict__ Al,
                     const __nv_bfloat16* __restrict__ Bh, const __nv_bfloat16* __restrict__ Bl,
                     float* __restrict__ C, int N,
                     const float* __restrict__ fc, const float* __restrict__ fs)
{
    extern __shared__ char smem[];
    const uint32_t sbase = smem_u32(smem);
    const int tid  = threadIdx.x;
    const int lane = tid & 31, wid = tid >> 5;
    const int wm   = wid & 3,  wn  = wid >> 2;
    const int row0 = blockIdx.y << 7, col0 = blockIdx.x << 7;

    const __nv_bfloat16* Abh = Ah + (size_t)row0 * GK;
    const __nv_bfloat16* Abl = Al + (size_t)row0 * GK;
    const __nv_bfloat16* Bbh = Bh + (size_t)col0 * GK;
    const __nv_bfloat16* Bbl = Bl + (size_t)col0 * GK;

    float acc[2][8][4];
    #pragma unroll
    for (int mi = 0; mi < 2; mi++)
        #pragma unroll
        for (int ni = 0; ni < 8; ni++)
            #pragma unroll
            for (int e = 0; e < 4; e++) acc[mi][ni][e] = 0.f;

    const uint32_t a_row = wm * 32 + (lane & 15);
    const uint32_t a_col = (lane >> 4) << 4;
    const uint32_t b_rowb = wn * 64 + (lane & 7) + ((lane >> 4) << 3);
    const uint32_t b_col  = ((lane >> 3) & 1) << 4;

    load_stage(Abh, Abl, Bbh, Bbl, 0, sbase, tid);
    CP_COMMIT();

    for (int blk = 0; blk < NKB; blk++) {
        const uint32_t buf = sbase + (uint32_t)(blk & 1) * STAGE_BY;
        if (blk + 1 < NKB) {
            load_stage(Abh, Abl, Bbh, Bbl, (blk + 1) * BK,
                       sbase + (uint32_t)((blk + 1) & 1) * STAGE_BY, tid);
            CP_COMMIT();
            CP_WAIT(1);
        } else {
            CP_WAIT(0);
        }
        __syncthreads();

        #pragma unroll
        for (int ks = 0; ks < 2; ks++) {
            const uint32_t koff = ks * 32;
            uint32_t ah[2][4], al[2][4];
            #pragma unroll
            for (int mi = 0; mi < 2; mi++) {
                const uint32_t aaddr = buf + SOFF_AH + (a_row + mi * 16) * TPITCH + koff + a_col;
                ldsm4(ah[mi], aaddr);
                ldsm4(al[mi], aaddr + (SOFF_AL - SOFF_AH));
            }
            uint32_t bh[4][4], bl[4][4];
            #pragma unroll
            for (int nq = 0; nq < 4; nq++) {
                const uint32_t baddr = buf + SOFF_BH + (b_rowb + nq * 16) * TPITCH + koff + b_col;
                ldsm4(bh[nq], baddr);
                ldsm4(bl[nq], baddr + (SOFF_BL - SOFF_BH));
            }
            #pragma unroll
            for (int mi = 0; mi < 2; mi++)
                #pragma unroll
                for (int nq = 0; nq < 4; nq++)
                    #pragma unroll
                    for (int hf = 0; hf < 2; hf++) {
                        const int ni = nq * 2 + hf;
                        const uint32_t b0h = bh[nq][hf * 2], b1h = bh[nq][hf * 2 + 1];
                        const uint32_t b0l = bl[nq][hf * 2], b1l = bl[nq][hf * 2 + 1];
                        mma16816(acc[mi][ni], ah[mi], b0h, b1h);
                        mma16816(acc[mi][ni], ah[mi], b0l, b1l);
                        mma16816(acc[mi][ni], al[mi], b0h, b1h);
                    }
        }
        __syncthreads();
    }

    const int lr = lane >> 2;
    const int lc = (lane & 3) << 1;
    #pragma unroll
    for (int mi = 0; mi < 2; mi++) {
        #pragma unroll
        for (int ni = 0; ni < 8; ni++) {
            float* d = acc[mi][ni];
            const int r0  = row0 + wm * 32 + mi * 16 + lr;
            const int r1  = r0 + 8;
            const int col = col0 + wn * 64 + ni * 8 + lc;
            if (ROPE) {
                const int p = (col & (HDIM - 1)) >> 1;
                {
                    const int t = r0 & (T_SZ - 1);
                    const float cz = fc[t * (HDIM / 2) + p];
                    const float sz = fs[t * (HDIM / 2) + p];
                    const float xr = d[0], xi = d[1];
                    d[0] = xr * cz - xi * sz;
                    d[1] = xr * sz + xi * cz;
                }
                {
                    const int t = r1 & (T_SZ - 1);
                    const float cz = fc[t * (HDIM / 2) + p];
                    const float sz = fs[t * (HDIM / 2) + p];
                    const float xr = d[2], xi = d[3];
                    d[2] = xr * cz - xi * sz;
                    d[3] = xr * sz + xi * cz;
                }
            }
            *(float2*)(C + (size_t)r0 * N + col) = make_float2(d[0], d[1]);
            *(float2*)(C + (size_t)r1 * N + col) = make_float2(d[2], d[3]);
        }
    }
}

// ================= tensor-core flash attention ===============================
// q-tile 128 (8 warps x 16 rows), k-tile 64, 3-pass hi/lo mma for S and PV.
// Per-row softmax stats entirely in registers (row owned by one warp).
#define QPITCH 272                    // 128 bf16 = 256B + 16 pad
#define VPITCH 144                    // 64 bf16 = 128B + 16 pad
#define SM_QH  0
#define SM_QL  (128 * QPITCH)         // 34816
#define SM_KV  (2 * 128 * QPITCH)     // 69632
#define OFF_KH 0
#define OFF_KL (64 * QPITCH)          // 17408
#define OFF_VH (2 * 64 * QPITCH)      // 34816
#define OFF_VL (OFF_VH + 128 * VPITCH) // 53248
#define KVBUF  (OFF_VL + 128 * VPITCH) // 71680
#define FLASH2_SMEM (SM_KV + 2 * KVBUF) // 212992

__device__ __forceinline__ void flash_load_kv(
    const __nv_bfloat16* __restrict__ Kh, const __nv_bfloat16* __restrict__ Kl,
    const __nv_bfloat16* __restrict__ Vth, const __nv_bfloat16* __restrict__ Vtl,
    int b, int kvh, int kt, uint32_t buf, int tid)
{
    const char* gkh = (const char*)(Kh + (size_t)(b * T_SZ + kt * 64) * KVDIM + kvh * HDIM);
    const char* gkl = (const char*)(Kl + (size_t)(b * T_SZ + kt * 64) * KVDIM + kvh * HDIM);
    #pragma unroll
    for (int s = 0; s < 4; s++) {
        const int u = tid + s * 256;           // 0..1023
        const int r = u >> 4, c = (u & 15) << 4;
        CP_ASYNC16(buf + OFF_KH + r * QPITCH + c, gkh + (size_t)r * (KVDIM * 2) + c);
        CP_ASYNC16(buf + OFF_KL + r * QPITCH + c, gkl + (size_t)r * (KVDIM * 2) + c);
    }
    const char* gvh = (const char*)(Vth + ((size_t)(b * KVHEAD + kvh) * HDIM) * T_SZ + kt * 64);
    const char* gvl = (const char*)(Vtl + ((size_t)(b * KVHEAD + kvh) * HDIM) * T_SZ + kt * 64);
    #pragma unroll
    for (int s = 0; s < 4; s++) {
        const int u = tid + s * 256;
        const int r = u >> 3, c = (u & 7) << 4;
        CP_ASYNC16(buf + OFF_VH + r * VPITCH + c, gvh + (size_t)r * (T_SZ * 2) + c);
        CP_ASYNC16(buf + OFF_VL + r * VPITCH + c, gvl + (size_t)r * (T_SZ * 2) + c);
    }
}

__global__ __launch_bounds__(256, 1)
void flash_mma_kernel(const __nv_bfloat16* __restrict__ Qh, const __nv_bfloat16* __restrict__ Ql,
                      const __nv_bfloat16* __restrict__ Kh, const __nv_bfloat16* __restrict__ Kl,
                      const __nv_bfloat16* __restrict__ Vth, const __nv_bfloat16* __restrict__ Vtl,
                      float* __restrict__ Og)
{
    extern __shared__ char smem[];
    const uint32_t sbase = smem_u32(smem);
    const int tid = threadIdx.x, lane = tid & 31, w = tid >> 5;
    const int qt = (int)gridDim.x - 1 - (int)blockIdx.x;   // heavy tiles first
    const int bh = blockIdx.y, b = bh >> 4, h = bh & 15, kvh = h >> 2;
    const int qrow0 = b * T_SZ + qt * 128;
    const int nkt = 2 * qt + 2;

    // prologue: stage Q (hi/lo) + KV tile 0
    {
        const char* gqh = (const char*)(Qh + (size_t)qrow0 * DIM_ + h * HDIM);
        const char* gql = (const char*)(Ql + (size_t)qrow0 * DIM_ + h * HDIM);
        #pragma unroll
        for (int s = 0; s < 8; s++) {
            const int u = tid + s * 256;       // 0..2047
            const int r = u >> 4, c = (u & 15) << 4;
            CP_ASYNC16(sbase + SM_QH + r * QPITCH + c, gqh + (size_t)r * (DIM_ * 2) + c);
            CP_ASYNC16(sbase + SM_QL + r * QPITCH + c, gql + (size_t)r * (DIM_ * 2) + c);
        }
    }
    flash_load_kv(Kh, Kl, Vth, Vtl, b, kvh, 0, sbase + SM_KV, tid);
    CP_COMMIT();

    float sm0 = -1e30f, sm1 = -1e30f, sl0 = 0.f, sl1 = 0.f;
    float vacc[16][4];
    #pragma unroll
    for (int ni = 0; ni < 16; ni++)
        #pragma unroll
        for (int e = 0; e < 4; e++) vacc[ni][e] = 0.f;

    const int r0l = w * 16 + (lane >> 2);
    const int r1l = r0l + 8;
    const uint32_t a_addr0 = sbase + SM_QH + (w * 16 + (lane & 15)) * QPITCH + ((lane >> 4) << 4);
    const uint32_t b_roff  = ((lane & 7) + ((lane >> 4) << 3));
    const uint32_t b_coff  = ((lane >> 3) & 1) << 4;

    CP_WAIT(0);
    __syncthreads();

    for (int kt = 0; kt < nkt; kt++) {
        const uint32_t buf = sbase + SM_KV + (uint32_t)(kt & 1) * KVBUF;
        if (kt + 1 < nkt) {
            flash_load_kv(Kh, Kl, Vth, Vtl, b, kvh, kt + 1,
                          sbase + SM_KV + (uint32_t)((kt + 1) & 1) * KVBUF, tid);
            CP_COMMIT();
        }

        // ---- S = Q K^T  (3-pass split) ----
        float sacc[8][4];
        #pragma unroll
        for (int nj = 0; nj < 8; nj++)
            #pragma unroll
            for (int e = 0; e < 4; e++) sacc[nj][e] = 0.f;

        #pragma unroll
        for (int ks = 0; ks < 8; ks++) {
            uint32_t qh4[4], ql4[4];
            const uint32_t aaddr = a_addr0 + ks * 32;
            ldsm4(qh4, aaddr);
            ldsm4(ql4, aaddr + (SM_QL - SM_QH));
            #pragma unroll
            for (int nq = 0; nq < 4; nq++) {
                uint32_t kh4[4], kl4[4];
                const uint32_t baddr = buf + OFF_KH + (nq * 16 + b_roff) * QPITCH + ks * 32 + b_coff;
                ldsm4(kh4, baddr);
                ldsm4(kl4, baddr + (OFF_KL - OFF_KH));
                mma16816(sacc[nq * 2],     qh4, kh4[0], kh4[1]);
                mma16816(sacc[nq * 2 + 1], qh4, kh4[2], kh4[3]);
                mma16816(sacc[nq * 2],     qh4, kl4[0], kl4[1]);
                mma16816(sacc[nq * 2 + 1], qh4, kl4[2], kl4[3]);
                mma16816(sacc[nq * 2],     ql4, kh4[0], kh4[1]);
                mma16816(sacc[nq * 2 + 1], ql4, kh4[2], kh4[3]);
            }
        }

        // ---- causal mask (diagonal k-tiles only) ----
        if (kt >= 2 * qt) {
            const int coff = kt * 64 - qt * 128;
            #pragma unroll
            for (int nj = 0; nj < 8; nj++) {
                const int c0 = coff + nj * 8 + (lane & 3) * 2;
                if (c0     > r0l) sacc[nj][0] = -1e30f;
                if (c0 + 1 > r0l) sacc[nj][1] = -1e30f;
                if (c0     > r1l) sacc[nj][2] = -1e30f;
                if (c0 + 1 > r1l) sacc[nj][3] = -1e30f;
            }
        }

        // ---- online softmax (row stats in registers, bfly over lane&3) ----
        float mx0 = -1e30f, mx1 = -1e30f;
        #pragma unroll
        for (int nj = 0; nj < 8; nj++) {
            mx0 = fmaxf(mx0, fmaxf(sacc[nj][0], sacc[nj][1]));
            mx1 = fmaxf(mx1, fmaxf(sacc[nj][2], sacc[nj][3]));
        }
        mx0 = fmaxf(mx0, __shfl_xor_sync(0xFFFFFFFFu, mx0, 1));
        mx0 = fmaxf(mx0, __shfl_xor_sync(0xFFFFFFFFu, mx0, 2));
        mx1 = fmaxf(mx1, __shfl_xor_sync(0xFFFFFFFFu, mx1, 1));
        mx1 = fmaxf(mx1, __shfl_xor_sync(0xFFFFFFFFu, mx1, 2));
        const float mn0 = fmaxf(sm0, mx0), mn1 = fmaxf(sm1, mx1);
        const float al0 = __expf(sm0 - mn0), al1 = __expf(sm1 - mn1);
        sm0 = mn0; sm1 = mn1;

        // P = exp(S - m), pack to hi/lo A fragments, accumulate row sums
        uint32_t pah[4][4], pal[4][4];
        float ls0 = 0.f, ls1 = 0.f;
        #pragma unroll
        for (int j = 0; j < 4; j++) {
            #pragma unroll
            for (int t = 0; t < 2; t++) {
                const int nj = 2 * j + t;
                const float p0 = __expf(sacc[nj][0] - mn0);
                const float p1 = __expf(sacc[nj][1] - mn0);
                const float p2 = __expf(sacc[nj][2] - mn1);
                const float p3 = __expf(sacc[nj][3] - mn1);
                ls0 += p0 + p1;
                ls1 += p2 + p3;
                split2(p0, p1, pah[j][t * 2],     pal[j][t * 2]);
                split2(p2, p3, pah[j][t * 2 + 1], pal[j][t * 2 + 1]);
            }
        }
        ls0 += __shfl_xor_sync(0xFFFFFFFFu, ls0, 1);
        ls0 += __shfl_xor_sync(0xFFFFFFFFu, ls0, 2);
        ls1 += __shfl_xor_sync(0xFFFFFFFFu, ls1, 1);
        ls1 += __shfl_xor_sync(0xFFFFFFFFu, ls1, 2);
        sl0 = sl0 * al0 + ls0;
        sl1 = sl1 * al1 + ls1;

        // rescale O
        #pragma unroll
        for (int ni = 0; ni < 16; ni++) {
            vacc[ni][0] *= al0; vacc[ni][1] *= al0;
            vacc[ni][2] *= al1; vacc[ni][3] *= al1;
        }

        // ---- O += P V  (3-pass split; B = V^T [d][t]) ----
        #pragma unroll
        for (int j = 0; j < 4; j++) {
            #pragma unroll
            for (int nq = 0; nq < 8; nq++) {
                uint32_t vh4[4], vl4[4];
                const uint32_t vaddr = buf + OFF_VH + (nq * 16 + b_roff) * VPITCH + j * 32 + b_coff;
                ldsm4(vh4, vaddr);
                ldsm4(vl4, vaddr + (OFF_VL - OFF_VH));
                mma16816(vacc[nq * 2],     pah[j], vh4[0], vh4[1]);
                mma16816(vacc[nq * 2 + 1], pah[j], vh4[2], vh4[3]);
                mma16816(vacc[nq * 2],     pah[j], vl4[0], vl4[1]);
                mma16816(vacc[nq * 2 + 1], pah[j], vl4[2], vl4[3]);
                mma16816(vacc[nq * 2],     pal[j], vh4[0], vh4[1]);
                mma16816(vacc[nq * 2 + 1], pal[j], vh4[2], vh4[3]);
            }
        }

        if (kt + 1 < nkt) CP_WAIT(0);
        __syncthreads();
    }

    // ---- epilogue ----
    const float inv0 = 1.f / sl0, inv1 = 1.f / sl1;
    float* o0 = Og + (size_t)(qrow0 + r0l) * DIM_ + h * HDIM;
    float* o1 = Og + (size_t)(qrow0 + r1l) * DIM_ + h * HDIM;
    #pragma unroll
    for (int ni = 0; ni < 16; ni++) {
        const int col = ni * 8 + (lane & 3) * 2;
        *(float2*)(o0 + col) = make_float2(vacc[ni][0] * inv0, vacc[ni][1] * inv0);
        *(float2*)(o1 + col) = make_float2(vacc[ni][2] * inv1, vacc[ni][3] * inv1);
    }
}

// ================= launch ====================================================
extern "C" void kernel_launch(void* const* d_in, const int* in_sizes, int n_in,
                              void* d_out, int out_size)
{
    const float* x  = (const float*)d_in[0];
    const float* fc = (const float*)d_in[1];
    const float* fs = (const float*)d_in[2];
    const float* wq = (const float*)d_in[3];
    const float* wk = (const float*)d_in[4];
    const float* wv = (const float*)d_in[5];
    const float* wo = (const float*)d_in[6];
    float* out = (float*)d_out;

    float *q, *k, *v, *att;
    cudaGetSymbolAddress((void**)&q,   g_q);
    cudaGetSymbolAddress((void**)&k,   g_k);
    cudaGetSymbolAddress((void**)&v,   g_v);
    cudaGetSymbolAddress((void**)&att, g_att);
    __nv_bfloat16 *xh, *xl, *wqth, *wqtl, *wkth, *wktl, *wvth, *wvtl, *woth, *wotl, *ath, *atl;
    __nv_bfloat16 *qh, *ql, *kh, *kl, *vth, *vtl;
    cudaGetSymbolAddress((void**)&xh,   g_xh);   cudaGetSymbolAddress((void**)&xl,   g_xl);
    cudaGetSymbolAddress((void**)&wqth, g_wqth); cudaGetSymbolAddress((void**)&wqtl, g_wqtl);
    cudaGetSymbolAddress((void**)&wkth, g_wkth); cudaGetSymbolAddress((void**)&wktl, g_wktl);
    cudaGetSymbolAddress((void**)&wvth, g_wvth); cudaGetSymbolAddress((void**)&wvtl, g_wvtl);
    cudaGetSymbolAddress((void**)&woth, g_woth); cudaGetSymbolAddress((void**)&wotl, g_wotl);
    cudaGetSymbolAddress((void**)&ath,  g_ath);  cudaGetSymbolAddress((void**)&atl,  g_atl);
    cudaGetSymbolAddress((void**)&qh,   g_qh);   cudaGetSymbolAddress((void**)&ql,   g_ql);
    cudaGetSymbolAddress((void**)&kh,   g_kh);   cudaGetSymbolAddress((void**)&kl,   g_kl);
    cudaGetSymbolAddress((void**)&vth,  g_vth);  cudaGetSymbolAddress((void**)&vtl,  g_vtl);

    cudaFuncSetAttribute(mma_gemm_kernel<true>,  cudaFuncAttributeMaxDynamicSharedMemorySize,
                         GEMM_SMEM);
    cudaFuncSetAttribute(mma_gemm_kernel<false>, cudaFuncAttributeMaxDynamicSharedMemorySize,
                         GEMM_SMEM);
    cudaFuncSetAttribute(flash_mma_kernel, cudaFuncAttributeMaxDynamicSharedMemorySize,
                         FLASH2_SMEM);

    const int n4x = MROWS * DIM_ / 4;          // 2M
    const int n4k = MROWS * KVDIM / 4;         // 512K
    const float qscale = 0.08838834764831845f; // 1/sqrt(128)

    split_kernel<<<n4x / 256, 256>>>(x, xh, xl, n4x, 1.f);
    tsplit_kernel<<<dim3(DIM_  / 32, DIM_ / 32), 256>>>(wq, wqth, wqtl, DIM_, DIM_);
    tsplit_kernel<<<dim3(KVDIM / 32, DIM_ / 32), 256>>>(wk, wkth, wktl, DIM_, KVDIM);
    tsplit_kernel<<<dim3(KVDIM / 32, DIM_ / 32), 256>>>(wv, wvth, wvtl, DIM_, KVDIM);
    tsplit_kernel<<<dim3(DIM_  / 32, DIM_ / 32), 256>>>(wo, woth, wotl, DIM_, DIM_);

    mma_gemm_kernel<true ><<<dim3(DIM_  / 128, MROWS / 128), 256, GEMM_SMEM>>>(
        xh, xl, wqth, wqtl, q, DIM_,  fc, fs);
    mma_gemm_kernel<true ><<<dim3(KVDIM / 128, MROWS / 128), 256, GEMM_SMEM>>>(
        xh, xl, wkth, wktl, k, KVDIM, fc, fs);
    mma_gemm_kernel<false><<<dim3(KVDIM / 128, MROWS / 128), 256, GEMM_SMEM>>>(
        xh, xl, wvth, wvtl, v, KVDIM, nullptr, nullptr);

    // convert flash inputs: Q (scale folded), K, V^T
    split_kernel<<<n4x / 256, 256>>>(q, qh, ql, n4x, qscale);
    split_kernel<<<n4k / 256, 256>>>(k, kh, kl, n4k, 1.f);
    vtsplit_kernel<<<dim3(T_SZ / 32, KVDIM / 32, B_SZ), 256>>>(v, vth, vtl);

    flash_mma_kernel<<<dim3(T_SZ / 128, B_SZ * NHEAD), 256, FLASH2_SMEM>>>(
        qh, ql, kh, kl, vth, vtl, att);

    split_kernel<<<n4x / 256, 256>>>(att, ath, atl, n4x, 1.f);
    mma_gemm_kernel<false><<<dim3(DIM_ / 128, MROWS / 128), 256, GEMM_SMEM>>>(
        ath, atl, woth, wotl, out, DIM_, nullptr, nullptr);
}